// round 14
// baseline (speedup 1.0000x reference)
#include <cuda_runtime.h>
#include <cstdint>
#include <cstring>

#define NTOK 16384
#define DMODEL 2048
#define NEXP 64
#define CAP 512

#define BM 128
#define BN 64
#define BK 32
#define NSEG 4
#define KSEG (DMODEL / NSEG)   // 512

// Scratch (allocation-free rule: device globals).
__device__ float g_partial[(size_t)NSEG * NTOK * NEXP];  // [seg][t][e], no bias
__device__ float g_logitsT[(size_t)NEXP * NTOK];         // [e][t]
__device__ float g_probsT[(size_t)NEXP * NTOK];          // [e][t]

// ---------------------------------------------------------------------------
// f32x2 helpers (per-lane IEEE RN, bit-identical to scalar fmaf/fadd).
// ---------------------------------------------------------------------------
__device__ __forceinline__ unsigned long long pack_dup(float w) {
    float2 f = make_float2(w, w);
    unsigned long long r;
    memcpy(&r, &f, 8);
    return r;
}
__device__ __forceinline__ float lo32(unsigned long long v) {
    return __uint_as_float((unsigned int)v);
}
__device__ __forceinline__ float hi32(unsigned long long v) {
    return __uint_as_float((unsigned int)(v >> 32));
}
__device__ __forceinline__ void fma2(unsigned long long& d,
                                     unsigned long long a, unsigned long long b) {
    asm("fma.rn.f32x2 %0, %1, %2, %3;" : "=l"(d) : "l"(a), "l"(b), "l"(d));
}

// ---------------------------------------------------------------------------
// GEMM partial: one CTA = (128-row M-tile, 512-K segment). Frozen ascending-k
// fma order within the segment; raw partial out (no bias).
// 512 threads, 2 CTAs/SM (8 warps/SMSP); per-thread 2 rows x 8 cols
// (cols {tx*4..+3} U {32+tx*4..+3} -> conflict-free LDS.128 on B).
// ---------------------------------------------------------------------------
__global__ __launch_bounds__(512, 2)
void gemm_partial_kernel(const float* __restrict__ x,
                         const float* __restrict__ W,
                         float* __restrict__ partial)
{
    __shared__ __align__(16) float As[2][BK][BM + 4];   // 132-float rows
    __shared__ __align__(16) float Bs[2][BK][BN + 4];   // 68-float rows

    const int tid = threadIdx.x;      // 0..511
    const int tx = tid & 7;
    const int ty = tid >> 3;          // 0..63, 2 rows each
    const int row0 = blockIdx.x * BM;
    const int kbase = blockIdx.y * KSEG;

    unsigned long long acc2[2][4];
#pragma unroll
    for (int r = 0; r < 2; r++)
#pragma unroll
        for (int jp = 0; jp < 4; jp++) acc2[r][jp] = 0ull;

    float4 ra[2];
    float4 rb;

    auto load_tile = [&](int kt) {
        const int k0 = kbase + kt * BK;
#pragma unroll
        for (int r = 0; r < 2; r++) {
            int f = tid + r * 512;
            int m = f >> 3;           // 0..127
            int kq = f & 7;
            ra[r] = *reinterpret_cast<const float4*>(
                x + (size_t)(row0 + m) * DMODEL + k0 + kq * 4);
        }
        {
            int n = tid >> 3;         // 0..63
            int kq = tid & 7;
            rb = *reinterpret_cast<const float4*>(
                W + (size_t)n * DMODEL + k0 + kq * 4);
        }
    };
    auto store_tile = [&](int buf) {
#pragma unroll
        for (int r = 0; r < 2; r++) {
            int f = tid + r * 512;
            int m = f >> 3;
            int kq = f & 7;
            As[buf][kq * 4 + 0][m] = ra[r].x;
            As[buf][kq * 4 + 1][m] = ra[r].y;
            As[buf][kq * 4 + 2][m] = ra[r].z;
            As[buf][kq * 4 + 3][m] = ra[r].w;
        }
        {
            int n = tid >> 3;
            int kq = tid & 7;
            Bs[buf][kq * 4 + 0][n] = rb.x;
            Bs[buf][kq * 4 + 1][n] = rb.y;
            Bs[buf][kq * 4 + 2][n] = rb.z;
            Bs[buf][kq * 4 + 3][n] = rb.w;
        }
    };

    const int NKT = KSEG / BK;   // 16 k-tiles per segment

    load_tile(0);
    store_tile(0);
    __syncthreads();

    for (int kt = 0; kt < NKT; kt++) {
        const int cur = kt & 1;
        if (kt < NKT - 1) load_tile(kt + 1);

#pragma unroll
        for (int k = 0; k < BK; k++) {
            float2 av = *reinterpret_cast<const float2*>(&As[cur][k][ty * 2]);
            ulonglong2 bl = *reinterpret_cast<const ulonglong2*>(&Bs[cur][k][tx * 4]);
            ulonglong2 bh = *reinterpret_cast<const ulonglong2*>(&Bs[cur][k][32 + tx * 4]);
            unsigned long long ad0 = pack_dup(av.x);
            unsigned long long ad1 = pack_dup(av.y);
            unsigned long long wp[4] = {bl.x, bl.y, bh.x, bh.y};
#pragma unroll
            for (int jp = 0; jp < 4; jp++) {
                fma2(acc2[0][jp], ad0, wp[jp]);
                fma2(acc2[1][jp], ad1, wp[jp]);
            }
        }

        if (kt < NKT - 1) {
            store_tile(cur ^ 1);
            __syncthreads();
        }
    }

    float* P = partial + (size_t)blockIdx.y * NTOK * NEXP;
    const int colL = tx * 4;
    const int colH = 32 + tx * 4;
#pragma unroll
    for (int r = 0; r < 2; r++) {
        int row = row0 + ty * 2 + r;
        float* pr = P + (size_t)row * NEXP;
        *reinterpret_cast<float4*>(pr + colL) =
            make_float4(lo32(acc2[r][0]), hi32(acc2[r][0]),
                        lo32(acc2[r][1]), hi32(acc2[r][1]));
        *reinterpret_cast<float4*>(pr + colH) =
            make_float4(lo32(acc2[r][2]), hi32(acc2[r][2]),
                        lo32(acc2[r][3]), hi32(acc2[r][3]));
    }
}

// ---------------------------------------------------------------------------
// Combine: logits = (((P0+P1)+P2)+P3) + b (exact sequential fold per elem).
// ---------------------------------------------------------------------------
__global__ __launch_bounds__(256, 8)
void combine_kernel(const float* __restrict__ partial,
                    const float* __restrict__ b,
                    float* __restrict__ logits,
                    float* __restrict__ logitsT)
{
    const int row = blockIdx.x * 256 + threadIdx.x;
    const int col = blockIdx.y * 4;
    const size_t off = (size_t)row * NEXP + col;

    float4 p0 = *reinterpret_cast<const float4*>(partial + off);
    float4 p1 = *reinterpret_cast<const float4*>(partial + (size_t)NTOK * NEXP + off);
    float4 p2 = *reinterpret_cast<const float4*>(partial + 2 * (size_t)NTOK * NEXP + off);
    float4 p3 = *reinterpret_cast<const float4*>(partial + 3 * (size_t)NTOK * NEXP + off);
    float4 bb = *reinterpret_cast<const float4*>(b + col);

    float4 o;
    o.x = __fadd_rn(__fadd_rn(__fadd_rn(__fadd_rn(p0.x, p1.x), p2.x), p3.x), bb.x);
    o.y = __fadd_rn(__fadd_rn(__fadd_rn(__fadd_rn(p0.y, p1.y), p2.y), p3.y), bb.y);
    o.z = __fadd_rn(__fadd_rn(__fadd_rn(__fadd_rn(p0.z, p1.z), p2.z), p3.z), bb.z);
    o.w = __fadd_rn(__fadd_rn(__fadd_rn(__fadd_rn(p0.w, p1.w), p2.w), p3.w), bb.w);

    *reinterpret_cast<float4*>(logits + off) = o;
    logitsT[(size_t)(col + 0) * NTOK + row] = o.x;
    logitsT[(size_t)(col + 1) * NTOK + row] = o.y;
    logitsT[(size_t)(col + 2) * NTOK + row] = o.z;
    logitsT[(size_t)(col + 3) * NTOK + row] = o.w;
}

// ---------------------------------------------------------------------------
// Cephes expf (float, no fma) — frozen bit-match to reference exp.
// ---------------------------------------------------------------------------
__device__ __forceinline__ float expf_cephes(float x) {
    const float LOG2EF = 1.44269504088896341f;
    const float Ca = 0.693359375f;
    const float Cb = -2.12194440e-4f;
    float fx = __fadd_rn(__fmul_rn(x, LOG2EF), 0.5f);
    fx = floorf(fx);
    float tmp = __fmul_rn(fx, Ca);
    float zc  = __fmul_rn(fx, Cb);
    float xx  = __fsub_rn(x, tmp);
    xx = __fsub_rn(xx, zc);
    float z2 = __fmul_rn(xx, xx);
    float y = 1.9875691500e-4f;
    y = __fadd_rn(__fmul_rn(y, xx), 1.3981999507e-3f);
    y = __fadd_rn(__fmul_rn(y, xx), 8.3334519073e-3f);
    y = __fadd_rn(__fmul_rn(y, xx), 4.1665795894e-2f);
    y = __fadd_rn(__fmul_rn(y, xx), 1.6666665459e-1f);
    y = __fadd_rn(__fmul_rn(y, xx), 5.0000001201e-1f);
    y = __fadd_rn(__fmul_rn(y, z2), xx);
    y = __fadd_rn(y, 1.0f);
    int n = (int)fx;
    float p2n = __int_as_float((n + 127) << 23);
    return __fmul_rn(y, p2n);
}

__device__ __forceinline__ float warp_max(float v) {
#pragma unroll
    for (int o = 16; o > 0; o >>= 1)
        v = fmaxf(v, __shfl_xor_sync(0xFFFFFFFFu, v, o));
    return v;
}

// ---------------------------------------------------------------------------
// Softmax(axis=0) + per-expert top-512. Frozen numeric recipe.
// ---------------------------------------------------------------------------
__global__ __launch_bounds__(1024, 1)
void softmax_topk_kernel(const float* __restrict__ logitsT,
                         float* __restrict__ probsT,
                         float* __restrict__ eprobs,
                         float* __restrict__ eidx)
{
    extern __shared__ float vals[];            // 16384 f32, token order
    __shared__ float sredf[32];
    __shared__ float sden;
    __shared__ int swcnt[32];
    __shared__ int sct;
    __shared__ int sgather;
    __shared__ unsigned long long sel[CAP];

    const int e = blockIdx.x;
    const int tid = threadIdx.x;
    const int lane = tid & 31;
    const int wid = tid >> 5;
    const float* Lt = logitsT + (size_t)e * NTOK;

    float lv[16];
    float mx = -3.4e38f;
#pragma unroll
    for (int c = 0; c < 4; c++) {
        float4 v = *reinterpret_cast<const float4*>(Lt + tid * 16 + c * 4);
        lv[c * 4 + 0] = v.x; lv[c * 4 + 1] = v.y;
        lv[c * 4 + 2] = v.z; lv[c * 4 + 3] = v.w;
    }
#pragma unroll
    for (int i = 0; i < 16; i++) mx = fmaxf(mx, lv[i]);
    mx = warp_max(mx);
    if (lane == 0) sredf[wid] = mx;
    __syncthreads();
    if (wid == 0) {
        float v = warp_max(sredf[lane]);
        if (lane == 0) sredf[0] = v;
    }
    __syncthreads();
    mx = sredf[0];
    __syncthreads();

    float pv[16];
#pragma unroll
    for (int i = 0; i < 16; i++)
        pv[i] = expf_cephes(__fsub_rn(lv[i], mx));
#pragma unroll
    for (int c = 0; c < 4; c++)
        *reinterpret_cast<float4*>(vals + tid * 16 + c * 4) =
            make_float4(pv[c * 4], pv[c * 4 + 1], pv[c * 4 + 2], pv[c * 4 + 3]);
    __syncthreads();

    // EXACT sequential denom (token-ascending), double-buffered LDS.
    if (tid == 0) {
        float a = 0.0f;
        float4 c0 = *reinterpret_cast<const float4*>(vals);
        float4 c1 = *reinterpret_cast<const float4*>(vals + 4);
        for (int t = 0; t < NTOK; t += 8) {
            float4 n0, n1;
            if (t + 8 < NTOK) {
                n0 = *reinterpret_cast<const float4*>(vals + t + 8);
                n1 = *reinterpret_cast<const float4*>(vals + t + 12);
            }
            a = __fadd_rn(a, c0.x); a = __fadd_rn(a, c0.y);
            a = __fadd_rn(a, c0.z); a = __fadd_rn(a, c0.w);
            a = __fadd_rn(a, c1.x); a = __fadd_rn(a, c1.y);
            a = __fadd_rn(a, c1.z); a = __fadd_rn(a, c1.w);
            c0 = n0; c1 = n1;
        }
        sden = a;
    }
    __syncthreads();
    const float dC = sden;

    unsigned int kh[16];
    float pcv[16];
#pragma unroll
    for (int i = 0; i < 16; i++) {
        pcv[i] = pv[i] / dC;
        kh[i] = ~__float_as_uint(pcv[i]);
    }
    float* Pt = probsT + (size_t)e * NTOK;
#pragma unroll
    for (int c = 0; c < 4; c++)
        *reinterpret_cast<float4*>(Pt + tid * 16 + c * 4) =
            make_float4(pcv[c * 4], pcv[c * 4 + 1], pcv[c * 4 + 2], pcv[c * 4 + 3]);

    auto block_count = [&](int c) -> int {
        c = __reduce_add_sync(0xFFFFFFFFu, c);
        if (lane == 0) swcnt[wid] = c;
        __syncthreads();
        if (wid == 0) {
            int v = __reduce_add_sync(0xFFFFFFFFu, swcnt[lane]);
            if (lane == 0) sct = v;
        }
        __syncthreads();
        return sct;
    };

    // 0 < p <= 1 -> kh always has top two bits set: start at bit 29.
    unsigned int P = 0xC0000000u;
    for (int bi = 29; bi >= 0; bi--) {
        unsigned int T = P | (1u << bi);
        int c = 0;
#pragma unroll
        for (int i = 0; i < 16; i++) c += (kh[i] < T) ? 1 : 0;
        if (block_count(c) < CAP) P = T;
    }
    int cl = 0, ce = 0;
#pragma unroll
    for (int i = 0; i < 16; i++) {
        cl += (kh[i] < P) ? 1 : 0;
        ce += (kh[i] == P) ? 1 : 0;
    }
    const int c_less = block_count(cl);
    const int c_eq = block_count(ce);
    const int need = CAP - c_less;

    unsigned int I = 0xFFFFFFFFu;                 // take all ties (common case)
    if (c_less + c_eq != CAP) {
        I = 0u;
        for (int bi = 13; bi >= 0; bi--) {
            unsigned int T = I | (1u << bi);
            int c = 0;
#pragma unroll
            for (int i = 0; i < 16; i++)
                c += (kh[i] == P && (unsigned int)(tid * 16 + i) < T) ? 1 : 0;
            if (block_count(c) < need) I = T;
        }
    }

    if (tid == 0) sgather = 0;
    __syncthreads();
#pragma unroll
    for (int i = 0; i < 16; i++) {
        unsigned int idx = (unsigned int)(tid * 16 + i);
        if (kh[i] < P || (kh[i] == P && idx <= I)) {
            int pos = atomicAdd(&sgather, 1);
            sel[pos] = ((unsigned long long)kh[i] << 32) | idx;
        }
    }
    __syncthreads();

    for (int k2 = 2; k2 <= CAP; k2 <<= 1) {
        for (int j = k2 >> 1; j > 0; j >>= 1) {
            if (tid < CAP) {
                int i = tid;
                int ixj = i ^ j;
                if (ixj > i) {
                    unsigned long long a = sel[i];
                    unsigned long long c = sel[ixj];
                    bool up = ((i & k2) == 0);
                    if ((a > c) == up) { sel[i] = c; sel[ixj] = a; }
                }
            }
            __syncthreads();
        }
    }

    if (tid < CAP) {
        unsigned long long key = sel[tid];
        unsigned int t = (unsigned int)(key & 0xFFFFFFFFull);
        unsigned int us = ~(unsigned int)(key >> 32);
        eprobs[(size_t)e * CAP + tid] = __uint_as_float(us);
        eidx[(size_t)e * CAP + tid] = (float)t;
    }
}

// ---------------------------------------------------------------------------
// Transpose probsT [64][16384] -> probs [16384][64].
// ---------------------------------------------------------------------------
__global__ __launch_bounds__(256, 4)
void transpose_kernel(const float* __restrict__ probsT,
                      float* __restrict__ probs)
{
    __shared__ float tile[32][33];
    const int t0 = blockIdx.x * 32;
    const int e0 = blockIdx.y * 32;
    const int tx = threadIdx.x;
    const int ty = threadIdx.y;

#pragma unroll
    for (int r = 0; r < 4; r++) {
        int e = e0 + ty + r * 8;
        tile[ty + r * 8][tx] = probsT[(size_t)e * NTOK + t0 + tx];
    }
    __syncthreads();
#pragma unroll
    for (int r = 0; r < 4; r++) {
        int t = t0 + ty + r * 8;
        probs[(size_t)t * NEXP + e0 + tx] = tile[tx][ty + r * 8];
    }
}

// ---------------------------------------------------------------------------
extern "C" void kernel_launch(void* const* d_in, const int* in_sizes, int n_in,
                              void* d_out, int out_size)
{
    const float* x = (const float*)d_in[0];
    const float* W = (const float*)d_in[1];
    const float* b = (const float*)d_in[2];

    float* out = (float*)d_out;
    float* logits = out;
    float* probs  = out + (size_t)NTOK * NEXP;
    float* eprobs = out + 2 * (size_t)NTOK * NEXP;
    float* eidx   = eprobs + (size_t)NEXP * CAP;

    float* partial = nullptr;
    float* logitsT = nullptr;
    float* probsT  = nullptr;
    cudaGetSymbolAddress((void**)&partial, g_partial);
    cudaGetSymbolAddress((void**)&logitsT, g_logitsT);
    cudaGetSymbolAddress((void**)&probsT, g_probsT);

    dim3 ggrid(NTOK / BM, NSEG);
    gemm_partial_kernel<<<ggrid, 512>>>(x, W, partial);

    dim3 cgrid(NTOK / 256, 16);
    combine_kernel<<<cgrid, 256>>>(partial, b, logits, logitsT);

    const int smem = NTOK * (int)sizeof(float);   // 64 KB
    cudaFuncSetAttribute(softmax_topk_kernel,
                         cudaFuncAttributeMaxDynamicSharedMemorySize, smem);
    softmax_topk_kernel<<<NEXP, 1024, smem>>>(logitsT, probsT, eprobs, eidx);

    dim3 tgrid(NTOK / 32, NEXP / 32);
    transpose_kernel<<<tgrid, dim3(32, 8)>>>(probsT, probs);
}

// round 15
// speedup vs baseline: 1.2668x; 1.2668x over previous
#include <cuda_runtime.h>
#include <cstdint>
#include <cstring>

#define NTOK 16384
#define DMODEL 2048
#define NEXP 64
#define CAP 512

#define BM 128
#define BN 64
#define BK 32
#define NSEG 4
#define KSEG (DMODEL / NSEG)   // 512

// Scratch (allocation-free rule: device globals).
__device__ float g_partial[(size_t)NSEG * NTOK * NEXP];  // [seg][t][e], no bias
__device__ float g_logitsT[(size_t)NEXP * NTOK];         // [e][t]
__device__ float g_probsT[(size_t)NEXP * NTOK];          // [e][t]

// ---------------------------------------------------------------------------
// f32x2 helpers (per-lane IEEE RN, bit-identical to scalar fmaf/fadd).
// ---------------------------------------------------------------------------
__device__ __forceinline__ unsigned long long pack_dup(float w) {
    float2 f = make_float2(w, w);
    unsigned long long r;
    memcpy(&r, &f, 8);
    return r;
}
__device__ __forceinline__ float lo32(unsigned long long v) {
    return __uint_as_float((unsigned int)v);
}
__device__ __forceinline__ float hi32(unsigned long long v) {
    return __uint_as_float((unsigned int)(v >> 32));
}
__device__ __forceinline__ void fma2(unsigned long long& d,
                                     unsigned long long a, unsigned long long b) {
    asm("fma.rn.f32x2 %0, %1, %2, %3;" : "=l"(d) : "l"(a), "l"(b), "l"(d));
}

// ---------------------------------------------------------------------------
// GEMM partial (R12 shape, best known): one CTA = (128-row M-tile, 512-K seg).
// Frozen ascending-k fma order; raw partial out. 256 threads, 2 CTAs/SM;
// per-thread 4 rows x 8 cols (cols {tx*4..+3} U {32+tx*4..+3}).
// ---------------------------------------------------------------------------
__global__ __launch_bounds__(256, 2)
void gemm_partial_kernel(const float* __restrict__ x,
                         const float* __restrict__ W,
                         float* __restrict__ partial)
{
    __shared__ __align__(16) float As[2][BK][BM + 4];
    __shared__ __align__(16) float Bs[2][BK][BN + 4];

    const int tid = threadIdx.x;
    const int tx = tid & 7;
    const int ty = tid >> 3;          // 0..31
    const int row0 = blockIdx.x * BM;
    const int kbase = blockIdx.y * KSEG;

    unsigned long long acc2[4][4];
#pragma unroll
    for (int r = 0; r < 4; r++)
#pragma unroll
        for (int jp = 0; jp < 4; jp++) acc2[r][jp] = 0ull;

    float4 ra[4];
    float4 rb[2];

    auto load_tile = [&](int kt) {
        const int k0 = kbase + kt * BK;
#pragma unroll
        for (int r = 0; r < 4; r++) {
            int f = tid + r * 256;
            int m = f >> 3;
            int kq = f & 7;
            ra[r] = *reinterpret_cast<const float4*>(
                x + (size_t)(row0 + m) * DMODEL + k0 + kq * 4);
        }
#pragma unroll
        for (int r = 0; r < 2; r++) {
            int f = tid + r * 256;
            int n = f >> 3;
            int kq = f & 7;
            rb[r] = *reinterpret_cast<const float4*>(
                W + (size_t)n * DMODEL + k0 + kq * 4);
        }
    };
    auto store_tile = [&](int buf) {
#pragma unroll
        for (int r = 0; r < 4; r++) {
            int f = tid + r * 256;
            int m = f >> 3;
            int kq = f & 7;
            As[buf][kq * 4 + 0][m] = ra[r].x;
            As[buf][kq * 4 + 1][m] = ra[r].y;
            As[buf][kq * 4 + 2][m] = ra[r].z;
            As[buf][kq * 4 + 3][m] = ra[r].w;
        }
#pragma unroll
        for (int r = 0; r < 2; r++) {
            int f = tid + r * 256;
            int n = f >> 3;
            int kq = f & 7;
            Bs[buf][kq * 4 + 0][n] = rb[r].x;
            Bs[buf][kq * 4 + 1][n] = rb[r].y;
            Bs[buf][kq * 4 + 2][n] = rb[r].z;
            Bs[buf][kq * 4 + 3][n] = rb[r].w;
        }
    };

    const int NKT = KSEG / BK;   // 16

    load_tile(0);
    store_tile(0);
    __syncthreads();

    for (int kt = 0; kt < NKT; kt++) {
        const int cur = kt & 1;
        if (kt < NKT - 1) load_tile(kt + 1);

#pragma unroll
        for (int k = 0; k < BK; k++) {
            float4 av = *reinterpret_cast<const float4*>(&As[cur][k][ty * 4]);
            ulonglong2 bl = *reinterpret_cast<const ulonglong2*>(&Bs[cur][k][tx * 4]);
            ulonglong2 bh = *reinterpret_cast<const ulonglong2*>(&Bs[cur][k][32 + tx * 4]);
            unsigned long long ad0 = pack_dup(av.x);
            unsigned long long ad1 = pack_dup(av.y);
            unsigned long long ad2 = pack_dup(av.z);
            unsigned long long ad3 = pack_dup(av.w);
            unsigned long long wp[4] = {bl.x, bl.y, bh.x, bh.y};
#pragma unroll
            for (int jp = 0; jp < 4; jp++) {
                fma2(acc2[0][jp], ad0, wp[jp]);
                fma2(acc2[1][jp], ad1, wp[jp]);
                fma2(acc2[2][jp], ad2, wp[jp]);
                fma2(acc2[3][jp], ad3, wp[jp]);
            }
        }

        if (kt < NKT - 1) {
            store_tile(cur ^ 1);
            __syncthreads();
        }
    }

    float* P = partial + (size_t)blockIdx.y * NTOK * NEXP;
    const int colL = tx * 4;
    const int colH = 32 + tx * 4;
#pragma unroll
    for (int r = 0; r < 4; r++) {
        int row = row0 + ty * 4 + r;
        float* pr = P + (size_t)row * NEXP;
        *reinterpret_cast<float4*>(pr + colL) =
            make_float4(lo32(acc2[r][0]), hi32(acc2[r][0]),
                        lo32(acc2[r][1]), hi32(acc2[r][1]));
        *reinterpret_cast<float4*>(pr + colH) =
            make_float4(lo32(acc2[r][2]), hi32(acc2[r][2]),
                        lo32(acc2[r][3]), hi32(acc2[r][3]));
    }
}

// ---------------------------------------------------------------------------
// Combine: logits = (((P0+P1)+P2)+P3) + b (exact sequential fold per elem).
// ---------------------------------------------------------------------------
__global__ __launch_bounds__(256, 8)
void combine_kernel(const float* __restrict__ partial,
                    const float* __restrict__ b,
                    float* __restrict__ logits,
                    float* __restrict__ logitsT)
{
    const int row = blockIdx.x * 256 + threadIdx.x;
    const int col = blockIdx.y * 4;
    const size_t off = (size_t)row * NEXP + col;

    float4 p0 = *reinterpret_cast<const float4*>(partial + off);
    float4 p1 = *reinterpret_cast<const float4*>(partial + (size_t)NTOK * NEXP + off);
    float4 p2 = *reinterpret_cast<const float4*>(partial + 2 * (size_t)NTOK * NEXP + off);
    float4 p3 = *reinterpret_cast<const float4*>(partial + 3 * (size_t)NTOK * NEXP + off);
    float4 bb = *reinterpret_cast<const float4*>(b + col);

    float4 o;
    o.x = __fadd_rn(__fadd_rn(__fadd_rn(__fadd_rn(p0.x, p1.x), p2.x), p3.x), bb.x);
    o.y = __fadd_rn(__fadd_rn(__fadd_rn(__fadd_rn(p0.y, p1.y), p2.y), p3.y), bb.y);
    o.z = __fadd_rn(__fadd_rn(__fadd_rn(__fadd_rn(p0.z, p1.z), p2.z), p3.z), bb.z);
    o.w = __fadd_rn(__fadd_rn(__fadd_rn(__fadd_rn(p0.w, p1.w), p2.w), p3.w), bb.w);

    *reinterpret_cast<float4*>(logits + off) = o;
    logitsT[(size_t)(col + 0) * NTOK + row] = o.x;
    logitsT[(size_t)(col + 1) * NTOK + row] = o.y;
    logitsT[(size_t)(col + 2) * NTOK + row] = o.z;
    logitsT[(size_t)(col + 3) * NTOK + row] = o.w;
}

// ---------------------------------------------------------------------------
// Cephes expf (float, no fma) — frozen bit-match to reference exp.
// ---------------------------------------------------------------------------
__device__ __forceinline__ float expf_cephes(float x) {
    const float LOG2EF = 1.44269504088896341f;
    const float Ca = 0.693359375f;
    const float Cb = -2.12194440e-4f;
    float fx = __fadd_rn(__fmul_rn(x, LOG2EF), 0.5f);
    fx = floorf(fx);
    float tmp = __fmul_rn(fx, Ca);
    float zc  = __fmul_rn(fx, Cb);
    float xx  = __fsub_rn(x, tmp);
    xx = __fsub_rn(xx, zc);
    float z2 = __fmul_rn(xx, xx);
    float y = 1.9875691500e-4f;
    y = __fadd_rn(__fmul_rn(y, xx), 1.3981999507e-3f);
    y = __fadd_rn(__fmul_rn(y, xx), 8.3334519073e-3f);
    y = __fadd_rn(__fmul_rn(y, xx), 4.1665795894e-2f);
    y = __fadd_rn(__fmul_rn(y, xx), 1.6666665459e-1f);
    y = __fadd_rn(__fmul_rn(y, xx), 5.0000001201e-1f);
    y = __fadd_rn(__fmul_rn(y, z2), xx);
    y = __fadd_rn(y, 1.0f);
    int n = (int)fx;
    float p2n = __int_as_float((n + 127) << 23);
    return __fmul_rn(y, p2n);
}

__device__ __forceinline__ float warp_max(float v) {
#pragma unroll
    for (int o = 16; o > 0; o >>= 1)
        v = fmaxf(v, __shfl_xor_sync(0xFFFFFFFFu, v, o));
    return v;
}

// ---------------------------------------------------------------------------
// Softmax(axis=0) + per-expert top-512. Frozen numeric recipe (cephes exp,
// token-ascending sequential fp32 denom, pc = pv/denom, top-512 by
// (~pc_bits, idx) ascending).
// NEW: the 30-round threshold search runs on the pv keys in warps 1..31
// (named barrier, 992 threads) OVERLAPPED with the serial denominator chain
// in warp 0. Monotonicity of /denom makes pv_512 -> B = round(pv_512/denom)
// the exact pc threshold value; post-chain work is only the tie fix-up.
// ---------------------------------------------------------------------------
__global__ __launch_bounds__(1024, 1)
void softmax_topk_kernel(const float* __restrict__ logitsT,
                         float* __restrict__ probsT,
                         float* __restrict__ eprobs,
                         float* __restrict__ eidx)
{
    extern __shared__ float vals[];            // 16384 f32, token order
    __shared__ float sredf[32];
    __shared__ float sden;
    __shared__ unsigned int sPpv;              // 512th-smallest ~pv_bits
    __shared__ float sBval;
    __shared__ int swcnt[32];
    __shared__ int sct;
    __shared__ int sgather;
    __shared__ unsigned long long sel[CAP];

    const int e = blockIdx.x;
    const int tid = threadIdx.x;
    const int lane = tid & 31;
    const int wid = tid >> 5;
    const float* Lt = logitsT + (size_t)e * NTOK;

    // ---- coalesced loads + block max ----
    float lv[16];
    float mx = -3.4e38f;
#pragma unroll
    for (int c = 0; c < 4; c++) {
        float4 v = *reinterpret_cast<const float4*>(Lt + tid * 16 + c * 4);
        lv[c * 4 + 0] = v.x; lv[c * 4 + 1] = v.y;
        lv[c * 4 + 2] = v.z; lv[c * 4 + 3] = v.w;
    }
#pragma unroll
    for (int i = 0; i < 16; i++) mx = fmaxf(mx, lv[i]);
    mx = warp_max(mx);
    if (lane == 0) sredf[wid] = mx;
    __syncthreads();
    if (wid == 0) {
        float v = warp_max(sredf[lane]);
        if (lane == 0) sredf[0] = v;
    }
    __syncthreads();
    mx = sredf[0];
    __syncthreads();

    // ---- exp (cephes), stash to smem ----
    float pv[16];
#pragma unroll
    for (int i = 0; i < 16; i++)
        pv[i] = expf_cephes(__fsub_rn(lv[i], mx));
#pragma unroll
    for (int c = 0; c < 4; c++)
        *reinterpret_cast<float4*>(vals + tid * 16 + c * 4) =
            make_float4(pv[c * 4], pv[c * 4 + 1], pv[c * 4 + 2], pv[c * 4 + 3]);
    __syncthreads();

    // ================= overlapped phase =================
    if (wid == 0) {
        // warp 0: EXACT sequential denom (token-ascending), double-buffered.
        if (lane == 0) {
            float a = 0.0f;
            float4 c0 = *reinterpret_cast<const float4*>(vals);
            float4 c1 = *reinterpret_cast<const float4*>(vals + 4);
            for (int t = 0; t < NTOK; t += 8) {
                float4 n0, n1;
                if (t + 8 < NTOK) {
                    n0 = *reinterpret_cast<const float4*>(vals + t + 8);
                    n1 = *reinterpret_cast<const float4*>(vals + t + 12);
                }
                a = __fadd_rn(a, c0.x); a = __fadd_rn(a, c0.y);
                a = __fadd_rn(a, c0.z); a = __fadd_rn(a, c0.w);
                a = __fadd_rn(a, c1.x); a = __fadd_rn(a, c1.y);
                a = __fadd_rn(a, c1.z); a = __fadd_rn(a, c1.w);
                c0 = n0; c1 = n1;
            }
            sden = a;
        }
    } else {
        // warps 1..31 (992 threads): find the 512th-smallest ~pv_bits key.
        const int s = tid - 32;       // 0..991
        unsigned int P = 0xC0000000u; // pv in (0,1] -> top 2 bits of ~bits set
        for (int bi = 29; bi >= 0; bi--) {
            unsigned int T = P | (1u << bi);
            int c = 0;
#pragma unroll
            for (int r = 0; r < 17; r++) {
                int t = s + 992 * r;
                if (t < NTOK) {
                    unsigned int kv = ~__float_as_uint(vals[t]);
                    c += (kv < T) ? 1 : 0;
                }
            }
            // group reduce over 31 warps (named barrier, 992 threads)
            c = __reduce_add_sync(0xFFFFFFFFu, c);
            if (lane == 0) swcnt[wid] = c;
            asm volatile("bar.sync 1, 992;" ::: "memory");
            if (wid == 1) {
                int v = (lane < 31) ? swcnt[lane + 1] : 0;
                v = __reduce_add_sync(0xFFFFFFFFu, v);
                if (lane == 0) sct = v;
            }
            asm volatile("bar.sync 1, 992;" ::: "memory");
            if (sct < CAP) P = T;
        }
        if (s == 0) sPpv = P;
    }
    __syncthreads();   // join: denom + pv threshold both ready

    const float dC = sden;

    // ---- pc for owned elements + coalesced probs write ----
    unsigned int kh[16];
    float pcv[16];
#pragma unroll
    for (int i = 0; i < 16; i++) {
        pcv[i] = pv[i] / dC;
        kh[i] = ~__float_as_uint(pcv[i]);
    }
    float* Pt = probsT + (size_t)e * NTOK;
#pragma unroll
    for (int c = 0; c < 4; c++)
        *reinterpret_cast<float4*>(Pt + tid * 16 + c * 4) =
            make_float4(pcv[c * 4], pcv[c * 4 + 1], pcv[c * 4 + 2], pcv[c * 4 + 3]);

    // ---- exact pc threshold value B = round(pv_512 / denom) ----
    if (tid == 0) sBval = __uint_as_float(~sPpv) / dC;
    __syncthreads();
    const unsigned int KB = ~__float_as_uint(sBval);

    auto block_count = [&](int c) -> int {
        c = __reduce_add_sync(0xFFFFFFFFu, c);
        if (lane == 0) swcnt[wid] = c;
        __syncthreads();
        if (wid == 0) {
            int v = __reduce_add_sync(0xFFFFFFFFu, swcnt[lane]);
            if (lane == 0) sct = v;
        }
        __syncthreads();
        return sct;
    };

    int cl = 0, ce = 0;
#pragma unroll
    for (int i = 0; i < 16; i++) {
        cl += (kh[i] < KB) ? 1 : 0;
        ce += (kh[i] == KB) ? 1 : 0;
    }
    const int c_less = block_count(cl);
    const int c_eq = block_count(ce);
    const int need = CAP - c_less;

    unsigned int I = 0xFFFFFFFFu;                 // take all ties (common case)
    if (c_less + c_eq != CAP) {
        I = 0u;
        for (int bi = 13; bi >= 0; bi--) {
            unsigned int T = I | (1u << bi);
            int c = 0;
#pragma unroll
            for (int i = 0; i < 16; i++)
                c += (kh[i] == KB && (unsigned int)(tid * 16 + i) < T) ? 1 : 0;
            if (block_count(c) < need) I = T;
        }
    }

    if (tid == 0) sgather = 0;
    __syncthreads();
#pragma unroll
    for (int i = 0; i < 16; i++) {
        unsigned int idx = (unsigned int)(tid * 16 + i);
        if (kh[i] < KB || (kh[i] == KB && idx <= I)) {
            int pos = atomicAdd(&sgather, 1);
            sel[pos] = ((unsigned long long)kh[i] << 32) | idx;
        }
    }
    __syncthreads();

    // ---- bitonic sort 512 ascending on (kh, idx) ----
    for (int k2 = 2; k2 <= CAP; k2 <<= 1) {
        for (int j = k2 >> 1; j > 0; j >>= 1) {
            if (tid < CAP) {
                int i = tid;
                int ixj = i ^ j;
                if (ixj > i) {
                    unsigned long long a = sel[i];
                    unsigned long long c = sel[ixj];
                    bool up = ((i & k2) == 0);
                    if ((a > c) == up) { sel[i] = c; sel[ixj] = a; }
                }
            }
            __syncthreads();
        }
    }

    if (tid < CAP) {
        unsigned long long key = sel[tid];
        unsigned int t = (unsigned int)(key & 0xFFFFFFFFull);
        unsigned int us = ~(unsigned int)(key >> 32);
        eprobs[(size_t)e * CAP + tid] = __uint_as_float(us);
        eidx[(size_t)e * CAP + tid] = (float)t;
    }
}

// ---------------------------------------------------------------------------
// Transpose probsT [64][16384] -> probs [16384][64].
// ---------------------------------------------------------------------------
__global__ __launch_bounds__(256, 4)
void transpose_kernel(const float* __restrict__ probsT,
                      float* __restrict__ probs)
{
    __shared__ float tile[32][33];
    const int t0 = blockIdx.x * 32;
    const int e0 = blockIdx.y * 32;
    const int tx = threadIdx.x;
    const int ty = threadIdx.y;

#pragma unroll
    for (int r = 0; r < 4; r++) {
        int e = e0 + ty + r * 8;
        tile[ty + r * 8][tx] = probsT[(size_t)e * NTOK + t0 + tx];
    }
    __syncthreads();
#pragma unroll
    for (int r = 0; r < 4; r++) {
        int t = t0 + ty + r * 8;
        probs[(size_t)t * NEXP + e0 + tx] = tile[tx][ty + r * 8];
    }
}

// ---------------------------------------------------------------------------
extern "C" void kernel_launch(void* const* d_in, const int* in_sizes, int n_in,
                              void* d_out, int out_size)
{
    const float* x = (const float*)d_in[0];
    const float* W = (const float*)d_in[1];
    const float* b = (const float*)d_in[2];

    float* out = (float*)d_out;
    float* logits = out;
    float* probs  = out + (size_t)NTOK * NEXP;
    float* eprobs = out + 2 * (size_t)NTOK * NEXP;
    float* eidx   = eprobs + (size_t)NEXP * CAP;

    float* partial = nullptr;
    float* logitsT = nullptr;
    float* probsT  = nullptr;
    cudaGetSymbolAddress((void**)&partial, g_partial);
    cudaGetSymbolAddress((void**)&logitsT, g_logitsT);
    cudaGetSymbolAddress((void**)&probsT, g_probsT);

    dim3 ggrid(NTOK / BM, NSEG);
    gemm_partial_kernel<<<ggrid, 256>>>(x, W, partial);

    dim3 cgrid(NTOK / 256, 16);
    combine_kernel<<<cgrid, 256>>>(partial, b, logits, logitsT);

    const int smem = NTOK * (int)sizeof(float);   // 64 KB
    cudaFuncSetAttribute(softmax_topk_kernel,
                         cudaFuncAttributeMaxDynamicSharedMemorySize, smem);
    softmax_topk_kernel<<<NEXP, 1024, smem>>>(logitsT, probsT, eprobs, eidx);

    dim3 tgrid(NTOK / 32, NEXP / 32);
    transpose_kernel<<<tgrid, dim3(32, 8)>>>(probsT, probs);
}

// round 16
// speedup vs baseline: 1.3523x; 1.0675x over previous
#include <cuda_runtime.h>
#include <cstdint>
#include <cstring>

#define NTOK 16384
#define DMODEL 2048
#define NEXP 64
#define CAP 512

#define BM 128
#define BN 64
#define BK 16
#define NSEG 4
#define KSEG (DMODEL / NSEG)   // 512

// Scratch (allocation-free rule: device globals).
__device__ float g_partial[(size_t)NSEG * NTOK * NEXP];  // [seg][t][e], no bias
__device__ float g_logitsT[(size_t)NEXP * NTOK];         // [e][t]
__device__ float g_probsT[(size_t)NEXP * NTOK];          // [e][t]

// ---------------------------------------------------------------------------
// f32x2 helpers (per-lane IEEE RN, bit-identical to scalar fmaf/fadd).
// ---------------------------------------------------------------------------
__device__ __forceinline__ unsigned long long pack_dup(float w) {
    float2 f = make_float2(w, w);
    unsigned long long r;
    memcpy(&r, &f, 8);
    return r;
}
__device__ __forceinline__ float lo32(unsigned long long v) {
    return __uint_as_float((unsigned int)v);
}
__device__ __forceinline__ float hi32(unsigned long long v) {
    return __uint_as_float((unsigned int)(v >> 32));
}
__device__ __forceinline__ void fma2(unsigned long long& d,
                                     unsigned long long a, unsigned long long b) {
    asm("fma.rn.f32x2 %0, %1, %2, %3;" : "=l"(d) : "l"(a), "l"(b), "l"(d));
}

// ---------------------------------------------------------------------------
// GEMM partial: one CTA = (128-row M-tile, 512-K segment). Frozen ascending-k
// fma order; raw partial out. BK=16, 256 threads, 3 CTAs/SM (6 warps/SMSP);
// per-thread 4 rows x 8 cols (cols {tx*4..+3} U {32+tx*4..+3} ->
// conflict-free LDS.128 on B). Double-buffered SMEM, register staging.
// ---------------------------------------------------------------------------
__global__ __launch_bounds__(256, 3)
void gemm_partial_kernel(const float* __restrict__ x,
                         const float* __restrict__ W,
                         float* __restrict__ partial)
{
    __shared__ __align__(16) float As[2][BK][BM + 4];   // 2*16*132*4 = 16.9 KB
    __shared__ __align__(16) float Bs[2][BK][BN + 4];   // 2*16*68*4  =  8.7 KB

    const int tid = threadIdx.x;
    const int tx = tid & 7;
    const int ty = tid >> 3;          // 0..31
    const int row0 = blockIdx.x * BM;
    const int kbase = blockIdx.y * KSEG;

    unsigned long long acc2[4][4];
#pragma unroll
    for (int r = 0; r < 4; r++)
#pragma unroll
        for (int jp = 0; jp < 4; jp++) acc2[r][jp] = 0ull;

    float4 ra[2];
    float4 rb;

    auto load_tile = [&](int kt) {
        const int k0 = kbase + kt * BK;
#pragma unroll
        for (int r = 0; r < 2; r++) {
            int f = tid + r * 256;
            int m = f >> 2;           // 0..127
            int kq = f & 3;           // 4 float4 per 16-float row
            ra[r] = *reinterpret_cast<const float4*>(
                x + (size_t)(row0 + m) * DMODEL + k0 + kq * 4);
        }
        {
            int n = tid >> 2;         // 0..63
            int kq = tid & 3;
            rb = *reinterpret_cast<const float4*>(
                W + (size_t)n * DMODEL + k0 + kq * 4);
        }
    };
    auto store_tile = [&](int buf) {
#pragma unroll
        for (int r = 0; r < 2; r++) {
            int f = tid + r * 256;
            int m = f >> 2;
            int kq = f & 3;
            As[buf][kq * 4 + 0][m] = ra[r].x;
            As[buf][kq * 4 + 1][m] = ra[r].y;
            As[buf][kq * 4 + 2][m] = ra[r].z;
            As[buf][kq * 4 + 3][m] = ra[r].w;
        }
        {
            int n = tid >> 2;
            int kq = tid & 3;
            Bs[buf][kq * 4 + 0][n] = rb.x;
            Bs[buf][kq * 4 + 1][n] = rb.y;
            Bs[buf][kq * 4 + 2][n] = rb.z;
            Bs[buf][kq * 4 + 3][n] = rb.w;
        }
    };

    const int NKT = KSEG / BK;   // 32 k-tiles per segment

    load_tile(0);
    store_tile(0);
    __syncthreads();

    for (int kt = 0; kt < NKT; kt++) {
        const int cur = kt & 1;
        if (kt < NKT - 1) load_tile(kt + 1);

#pragma unroll
        for (int k = 0; k < BK; k++) {
            float4 av = *reinterpret_cast<const float4*>(&As[cur][k][ty * 4]);
            ulonglong2 bl = *reinterpret_cast<const ulonglong2*>(&Bs[cur][k][tx * 4]);
            ulonglong2 bh = *reinterpret_cast<const ulonglong2*>(&Bs[cur][k][32 + tx * 4]);
            unsigned long long ad0 = pack_dup(av.x);
            unsigned long long ad1 = pack_dup(av.y);
            unsigned long long ad2 = pack_dup(av.z);
            unsigned long long ad3 = pack_dup(av.w);
            unsigned long long wp[4] = {bl.x, bl.y, bh.x, bh.y};
#pragma unroll
            for (int jp = 0; jp < 4; jp++) {
                fma2(acc2[0][jp], ad0, wp[jp]);
                fma2(acc2[1][jp], ad1, wp[jp]);
                fma2(acc2[2][jp], ad2, wp[jp]);
                fma2(acc2[3][jp], ad3, wp[jp]);
            }
        }

        if (kt < NKT - 1) {
            store_tile(cur ^ 1);
            __syncthreads();
        }
    }

    float* P = partial + (size_t)blockIdx.y * NTOK * NEXP;
    const int colL = tx * 4;
    const int colH = 32 + tx * 4;
#pragma unroll
    for (int r = 0; r < 4; r++) {
        int row = row0 + ty * 4 + r;
        float* pr = P + (size_t)row * NEXP;
        *reinterpret_cast<float4*>(pr + colL) =
            make_float4(lo32(acc2[r][0]), hi32(acc2[r][0]),
                        lo32(acc2[r][1]), hi32(acc2[r][1]));
        *reinterpret_cast<float4*>(pr + colH) =
            make_float4(lo32(acc2[r][2]), hi32(acc2[r][2]),
                        lo32(acc2[r][3]), hi32(acc2[r][3]));
    }
}

// ---------------------------------------------------------------------------
// Combine: logits = (((P0+P1)+P2)+P3) + b (exact sequential fold per elem).
// ---------------------------------------------------------------------------
__global__ __launch_bounds__(256, 8)
void combine_kernel(const float* __restrict__ partial,
                    const float* __restrict__ b,
                    float* __restrict__ logits,
                    float* __restrict__ logitsT)
{
    const int row = blockIdx.x * 256 + threadIdx.x;
    const int col = blockIdx.y * 4;
    const size_t off = (size_t)row * NEXP + col;

    float4 p0 = *reinterpret_cast<const float4*>(partial + off);
    float4 p1 = *reinterpret_cast<const float4*>(partial + (size_t)NTOK * NEXP + off);
    float4 p2 = *reinterpret_cast<const float4*>(partial + 2 * (size_t)NTOK * NEXP + off);
    float4 p3 = *reinterpret_cast<const float4*>(partial + 3 * (size_t)NTOK * NEXP + off);
    float4 bb = *reinterpret_cast<const float4*>(b + col);

    float4 o;
    o.x = __fadd_rn(__fadd_rn(__fadd_rn(__fadd_rn(p0.x, p1.x), p2.x), p3.x), bb.x);
    o.y = __fadd_rn(__fadd_rn(__fadd_rn(__fadd_rn(p0.y, p1.y), p2.y), p3.y), bb.y);
    o.z = __fadd_rn(__fadd_rn(__fadd_rn(__fadd_rn(p0.z, p1.z), p2.z), p3.z), bb.z);
    o.w = __fadd_rn(__fadd_rn(__fadd_rn(__fadd_rn(p0.w, p1.w), p2.w), p3.w), bb.w);

    *reinterpret_cast<float4*>(logits + off) = o;
    logitsT[(size_t)(col + 0) * NTOK + row] = o.x;
    logitsT[(size_t)(col + 1) * NTOK + row] = o.y;
    logitsT[(size_t)(col + 2) * NTOK + row] = o.z;
    logitsT[(size_t)(col + 3) * NTOK + row] = o.w;
}

// ---------------------------------------------------------------------------
// Cephes expf (float, no fma) — frozen bit-match to reference exp.
// ---------------------------------------------------------------------------
__device__ __forceinline__ float expf_cephes(float x) {
    const float LOG2EF = 1.44269504088896341f;
    const float Ca = 0.693359375f;
    const float Cb = -2.12194440e-4f;
    float fx = __fadd_rn(__fmul_rn(x, LOG2EF), 0.5f);
    fx = floorf(fx);
    float tmp = __fmul_rn(fx, Ca);
    float zc  = __fmul_rn(fx, Cb);
    float xx  = __fsub_rn(x, tmp);
    xx = __fsub_rn(xx, zc);
    float z2 = __fmul_rn(xx, xx);
    float y = 1.9875691500e-4f;
    y = __fadd_rn(__fmul_rn(y, xx), 1.3981999507e-3f);
    y = __fadd_rn(__fmul_rn(y, xx), 8.3334519073e-3f);
    y = __fadd_rn(__fmul_rn(y, xx), 4.1665795894e-2f);
    y = __fadd_rn(__fmul_rn(y, xx), 1.6666665459e-1f);
    y = __fadd_rn(__fmul_rn(y, xx), 5.0000001201e-1f);
    y = __fadd_rn(__fmul_rn(y, z2), xx);
    y = __fadd_rn(y, 1.0f);
    int n = (int)fx;
    float p2n = __int_as_float((n + 127) << 23);
    return __fmul_rn(y, p2n);
}

__device__ __forceinline__ float warp_max(float v) {
#pragma unroll
    for (int o = 16; o > 0; o >>= 1)
        v = fmaxf(v, __shfl_xor_sync(0xFFFFFFFFu, v, o));
    return v;
}

// ---------------------------------------------------------------------------
// Softmax(axis=0) + per-expert top-512. Frozen numeric recipe; pv-threshold
// bisection overlapped with the serial denominator chain (R15 design).
// ---------------------------------------------------------------------------
__global__ __launch_bounds__(1024, 1)
void softmax_topk_kernel(const float* __restrict__ logitsT,
                         float* __restrict__ probsT,
                         float* __restrict__ eprobs,
                         float* __restrict__ eidx)
{
    extern __shared__ float vals[];            // 16384 f32, token order
    __shared__ float sredf[32];
    __shared__ float sden;
    __shared__ unsigned int sPpv;              // 512th-smallest ~pv_bits
    __shared__ float sBval;
    __shared__ int swcnt[32];
    __shared__ int sct;
    __shared__ int sgather;
    __shared__ unsigned long long sel[CAP];

    const int e = blockIdx.x;
    const int tid = threadIdx.x;
    const int lane = tid & 31;
    const int wid = tid >> 5;
    const float* Lt = logitsT + (size_t)e * NTOK;

    float lv[16];
    float mx = -3.4e38f;
#pragma unroll
    for (int c = 0; c < 4; c++) {
        float4 v = *reinterpret_cast<const float4*>(Lt + tid * 16 + c * 4);
        lv[c * 4 + 0] = v.x; lv[c * 4 + 1] = v.y;
        lv[c * 4 + 2] = v.z; lv[c * 4 + 3] = v.w;
    }
#pragma unroll
    for (int i = 0; i < 16; i++) mx = fmaxf(mx, lv[i]);
    mx = warp_max(mx);
    if (lane == 0) sredf[wid] = mx;
    __syncthreads();
    if (wid == 0) {
        float v = warp_max(sredf[lane]);
        if (lane == 0) sredf[0] = v;
    }
    __syncthreads();
    mx = sredf[0];
    __syncthreads();

    float pv[16];
#pragma unroll
    for (int i = 0; i < 16; i++)
        pv[i] = expf_cephes(__fsub_rn(lv[i], mx));
#pragma unroll
    for (int c = 0; c < 4; c++)
        *reinterpret_cast<float4*>(vals + tid * 16 + c * 4) =
            make_float4(pv[c * 4], pv[c * 4 + 1], pv[c * 4 + 2], pv[c * 4 + 3]);
    __syncthreads();

    // ================= overlapped phase =================
    if (wid == 0) {
        if (lane == 0) {
            float a = 0.0f;
            float4 c0 = *reinterpret_cast<const float4*>(vals);
            float4 c1 = *reinterpret_cast<const float4*>(vals + 4);
            for (int t = 0; t < NTOK; t += 8) {
                float4 n0, n1;
                if (t + 8 < NTOK) {
                    n0 = *reinterpret_cast<const float4*>(vals + t + 8);
                    n1 = *reinterpret_cast<const float4*>(vals + t + 12);
                }
                a = __fadd_rn(a, c0.x); a = __fadd_rn(a, c0.y);
                a = __fadd_rn(a, c0.z); a = __fadd_rn(a, c0.w);
                a = __fadd_rn(a, c1.x); a = __fadd_rn(a, c1.y);
                a = __fadd_rn(a, c1.z); a = __fadd_rn(a, c1.w);
                c0 = n0; c1 = n1;
            }
            sden = a;
        }
    } else {
        const int s = tid - 32;       // 0..991
        unsigned int P = 0xC0000000u;
        for (int bi = 29; bi >= 0; bi--) {
            unsigned int T = P | (1u << bi);
            int c = 0;
#pragma unroll
            for (int r = 0; r < 17; r++) {
                int t = s + 992 * r;
                if (t < NTOK) {
                    unsigned int kv = ~__float_as_uint(vals[t]);
                    c += (kv < T) ? 1 : 0;
                }
            }
            c = __reduce_add_sync(0xFFFFFFFFu, c);
            if (lane == 0) swcnt[wid] = c;
            asm volatile("bar.sync 1, 992;" ::: "memory");
            if (wid == 1) {
                int v = (lane < 31) ? swcnt[lane + 1] : 0;
                v = __reduce_add_sync(0xFFFFFFFFu, v);
                if (lane == 0) sct = v;
            }
            asm volatile("bar.sync 1, 992;" ::: "memory");
            if (sct < CAP) P = T;
        }
        if (s == 0) sPpv = P;
    }
    __syncthreads();

    const float dC = sden;

    unsigned int kh[16];
    float pcv[16];
#pragma unroll
    for (int i = 0; i < 16; i++) {
        pcv[i] = pv[i] / dC;
        kh[i] = ~__float_as_uint(pcv[i]);
    }
    float* Pt = probsT + (size_t)e * NTOK;
#pragma unroll
    for (int c = 0; c < 4; c++)
        *reinterpret_cast<float4*>(Pt + tid * 16 + c * 4) =
            make_float4(pcv[c * 4], pcv[c * 4 + 1], pcv[c * 4 + 2], pcv[c * 4 + 3]);

    if (tid == 0) sBval = __uint_as_float(~sPpv) / dC;
    __syncthreads();
    const unsigned int KB = ~__float_as_uint(sBval);

    auto block_count = [&](int c) -> int {
        c = __reduce_add_sync(0xFFFFFFFFu, c);
        if (lane == 0) swcnt[wid] = c;
        __syncthreads();
        if (wid == 0) {
            int v = __reduce_add_sync(0xFFFFFFFFu, swcnt[lane]);
            if (lane == 0) sct = v;
        }
        __syncthreads();
        return sct;
    };

    int cl = 0, ce = 0;
#pragma unroll
    for (int i = 0; i < 16; i++) {
        cl += (kh[i] < KB) ? 1 : 0;
        ce += (kh[i] == KB) ? 1 : 0;
    }
    const int c_less = block_count(cl);
    const int c_eq = block_count(ce);
    const int need = CAP - c_less;

    unsigned int I = 0xFFFFFFFFu;
    if (c_less + c_eq != CAP) {
        I = 0u;
        for (int bi = 13; bi >= 0; bi--) {
            unsigned int T = I | (1u << bi);
            int c = 0;
#pragma unroll
            for (int i = 0; i < 16; i++)
                c += (kh[i] == KB && (unsigned int)(tid * 16 + i) < T) ? 1 : 0;
            if (block_count(c) < need) I = T;
        }
    }

    if (tid == 0) sgather = 0;
    __syncthreads();
#pragma unroll
    for (int i = 0; i < 16; i++) {
        unsigned int idx = (unsigned int)(tid * 16 + i);
        if (kh[i] < KB || (kh[i] == KB && idx <= I)) {
            int pos = atomicAdd(&sgather, 1);
            sel[pos] = ((unsigned long long)kh[i] << 32) | idx;
        }
    }
    __syncthreads();

    for (int k2 = 2; k2 <= CAP; k2 <<= 1) {
        for (int j = k2 >> 1; j > 0; j >>= 1) {
            if (tid < CAP) {
                int i = tid;
                int ixj = i ^ j;
                if (ixj > i) {
                    unsigned long long a = sel[i];
                    unsigned long long c = sel[ixj];
                    bool up = ((i & k2) == 0);
                    if ((a > c) == up) { sel[i] = c; sel[ixj] = a; }
                }
            }
            __syncthreads();
        }
    }

    if (tid < CAP) {
        unsigned long long key = sel[tid];
        unsigned int t = (unsigned int)(key & 0xFFFFFFFFull);
        unsigned int us = ~(unsigned int)(key >> 32);
        eprobs[(size_t)e * CAP + tid] = __uint_as_float(us);
        eidx[(size_t)e * CAP + tid] = (float)t;
    }
}

// ---------------------------------------------------------------------------
// Transpose probsT [64][16384] -> probs [16384][64].
// ---------------------------------------------------------------------------
__global__ __launch_bounds__(256, 4)
void transpose_kernel(const float* __restrict__ probsT,
                      float* __restrict__ probs)
{
    __shared__ float tile[32][33];
    const int t0 = blockIdx.x * 32;
    const int e0 = blockIdx.y * 32;
    const int tx = threadIdx.x;
    const int ty = threadIdx.y;

#pragma unroll
    for (int r = 0; r < 4; r++) {
        int e = e0 + ty + r * 8;
        tile[ty + r * 8][tx] = probsT[(size_t)e * NTOK + t0 + tx];
    }
    __syncthreads();
#pragma unroll
    for (int r = 0; r < 4; r++) {
        int t = t0 + ty + r * 8;
        probs[(size_t)t * NEXP + e0 + tx] = tile[tx][ty + r * 8];
    }
}

// ---------------------------------------------------------------------------
extern "C" void kernel_launch(void* const* d_in, const int* in_sizes, int n_in,
                              void* d_out, int out_size)
{
    const float* x = (const float*)d_in[0];
    const float* W = (const float*)d_in[1];
    const float* b = (const float*)d_in[2];

    float* out = (float*)d_out;
    float* logits = out;
    float* probs  = out + (size_t)NTOK * NEXP;
    float* eprobs = out + 2 * (size_t)NTOK * NEXP;
    float* eidx   = eprobs + (size_t)NEXP * CAP;

    float* partial = nullptr;
    float* logitsT = nullptr;
    float* probsT  = nullptr;
    cudaGetSymbolAddress((void**)&partial, g_partial);
    cudaGetSymbolAddress((void**)&logitsT, g_logitsT);
    cudaGetSymbolAddress((void**)&probsT, g_probsT);

    dim3 ggrid(NTOK / BM, NSEG);
    gemm_partial_kernel<<<ggrid, 256>>>(x, W, partial);

    dim3 cgrid(NTOK / 256, 16);
    combine_kernel<<<cgrid, 256>>>(partial, b, logits, logitsT);

    const int smem = NTOK * (int)sizeof(float);   // 64 KB
    cudaFuncSetAttribute(softmax_topk_kernel,
                         cudaFuncAttributeMaxDynamicSharedMemorySize, smem);
    softmax_topk_kernel<<<NEXP, 1024, smem>>>(logitsT, probsT, eprobs, eidx);

    dim3 tgrid(NTOK / 32, NEXP / 32);
    transpose_kernel<<<tgrid, dim3(32, 8)>>>(probsT, probs);
}